// round 12
// baseline (speedup 1.0000x reference)
#include <cuda_runtime.h>
#include <cuda_fp16.h>
#include <cstdint>

#define BATCH 4
#define SEQ 2048
#define DIM 1024
#define HEADS 16
#define DHEAD 64
#define INNER 1024
#define ROWS (BATCH * SEQ)      /* 8192 */
#define QKV_COLS (3 * INNER)    /* 3072 */
#define ATT_SCALE 0.125f

// ---------------- scratch (device globals) ----------------------------------
__device__ __half g_xf[(size_t)ROWS * DIM];
__device__ __half g_qkvf[(size_t)ROWS * QKV_COLS];
__device__ __half g_of[(size_t)ROWS * INNER];
__device__ __half g_wqkvf[(size_t)QKV_COLS * DIM];  // [N][K]
__device__ __half g_woutf[(size_t)DIM * INNER];     // [N][K]

// ---------------------------------------------------------------------------
__device__ __forceinline__ uint32_t pack_h2(float a, float b) {
    __half2 h = __floats2half2_rn(a, b);
    return *(uint32_t*)&h;
}

__global__ void cvt_f32_f16(const float* __restrict__ in,
                            __half* __restrict__ o, int n4)
{
    int i = blockIdx.x * blockDim.x + threadIdx.x;
    if (i >= n4) return;
    float4 v = ((const float4*)in)[i];
    ((uint2*)o)[i] = make_uint2(pack_h2(v.x, v.y), pack_h2(v.z, v.w));
}

// W[K][N] fp32 -> T[N][K] fp16, 32x32 tiles
__global__ void transpose_cvt(const float* __restrict__ W,
                              __half* __restrict__ T, int K, int N)
{
    __shared__ float t[32][33];
    int k0 = blockIdx.y * 32, n0 = blockIdx.x * 32;
    int tx = threadIdx.x, ty = threadIdx.y;
#pragma unroll
    for (int j = 0; j < 4; j++)
        t[ty + j * 8][tx] = W[(size_t)(k0 + ty + j * 8) * N + n0 + tx];
    __syncthreads();
#pragma unroll
    for (int j = 0; j < 4; j++) {
        float f = t[tx][ty + j * 8];
        T[(size_t)(n0 + ty + j * 8) * K + k0 + tx] = __float2half_rn(f);
    }
}

// ---------------------------------------------------------------------------
#define LDSM4(r0, r1, r2, r3, addr)                                          \
    asm volatile("ldmatrix.sync.aligned.m8n8.x4.shared.b16 {%0,%1,%2,%3}, [%4];" \
                 : "=r"(r0), "=r"(r1), "=r"(r2), "=r"(r3) : "r"(addr))
#define LDSM4T(r0, r1, r2, r3, addr)                                         \
    asm volatile("ldmatrix.sync.aligned.m8n8.x4.trans.shared.b16 {%0,%1,%2,%3}, [%4];" \
                 : "=r"(r0), "=r"(r1), "=r"(r2), "=r"(r3) : "r"(addr))
#define MMAS(d, a0, a1, a2, a3, b0, b1)                                      \
    asm volatile("mma.sync.aligned.m16n8k16.row.col.f32.f16.f16.f32 "        \
                 "{%0,%1,%2,%3},{%4,%5,%6,%7},{%8,%9},{%0,%1,%2,%3};"        \
                 : "+f"(d[0]), "+f"(d[1]), "+f"(d[2]), "+f"(d[3])            \
                 : "r"(a0), "r"(a1), "r"(a2), "r"(a3), "r"(b0), "r"(b1))
#define MMAA(d, a, b)                                                        \
    MMAS(d, (a)[0], (a)[1], (a)[2], (a)[3], (b)[0], (b)[1])
#define CPASYNC16(dst, src)                                                  \
    asm volatile("cp.async.cg.shared.global [%0], [%1], 16;" :: "r"(dst), "l"(src))

// ---------------------------------------------------------------------------
// fp16 HMMA GEMM: BM=BN=128, BK=64, 8 warps (32x64 tile), 3-stage cp.async
// ring, one sync per chunk, 2 CTAs/SM. Fragment loads SOFTWARE-PIPELINED:
// LDSM for ks+1 issued before MMAs of ks (double-buffered aF/bF).
// ---------------------------------------------------------------------------
#define GBM 128
#define GBN 128
#define GBK 64
#define GKP 72
#define GSTAGE (2 * GBM * GKP)
#define GNSTG 3
#define GSMEM (GNSTG * GSTAGE * 2)   /* 110592 bytes */

template <bool FP16_OUT>
__global__ __launch_bounds__(256, 2) void gemm_f16(
    const __half* __restrict__ A, const __half* __restrict__ B,
    const float* __restrict__ bias, float* __restrict__ C,
    __half* __restrict__ Ch, int M, int N, int K)
{
    extern __shared__ __half sm[];
    const int tid = threadIdx.x;
    const int lane = tid & 31, warp = tid >> 5;
    const int wm = warp >> 1, wn = warp & 1;
    const int brow = blockIdx.y * GBM, bcol = blockIdx.x * GBN;

    uint32_t sbase = (uint32_t)__cvta_generic_to_shared(sm);
    const int lrow = tid >> 3;
    const int lk = (tid & 7) << 3;

    float acc[2][8][4] = {};

    const int a_r = lane & 15;
    const int a_k = (lane >> 4) << 3;
    const int bg = lane >> 3;
    const int b_r = ((bg & 2) << 2) + (lane & 7);
    const int b_k = (bg & 1) << 3;
    const int NK = K / GBK;

    // per-warp base addresses inside a stage
    const uint32_t aoff = (uint32_t)((wm * 32 + a_r) * GKP + a_k) * 2;
    const uint32_t boff = (uint32_t)(GBM * GKP + (wn * 64 + b_r) * GKP + b_k) * 2;

    auto load_stage = [&](int st, int k0) {
        int base = st * GSTAGE;
#pragma unroll
        for (int i = 0; i < 4; i++) {
            int row = lrow + i * 32;
            uint32_t da = sbase + (uint32_t)(base + row * GKP + lk) * 2;
            CPASYNC16(da, A + (size_t)(brow + row) * K + k0 + lk);
            uint32_t db = sbase + (uint32_t)(base + GBM * GKP + row * GKP + lk) * 2;
            CPASYNC16(db, B + (size_t)(bcol + row) * K + k0 + lk);
        }
        asm volatile("cp.async.commit_group;");
    };

    load_stage(0, 0);
    load_stage(1, GBK);

    uint32_t aF[2][2][4], bF[2][8][2];

    for (int kc = 0; kc < NK; kc++) {
        if (kc + 1 < NK) {
            asm volatile("cp.async.wait_group 1;");
        } else {
            asm volatile("cp.async.wait_group 0;");
        }
        __syncthreads();

        if (kc + 2 < NK)
            load_stage((kc + 2) % GNSTG, (kc + 2) * GBK);

        const uint32_t stg = sbase + (uint32_t)((kc % GNSTG) * GSTAGE) * 2;

        // ---- prologue: fragments for ks=0 into buffer 0 ----
#pragma unroll
        for (int mt = 0; mt < 2; mt++) {
            uint32_t ad = stg + aoff + (uint32_t)(mt * 16 * GKP) * 2;
            LDSM4(aF[0][mt][0], aF[0][mt][1], aF[0][mt][2], aF[0][mt][3], ad);
        }
#pragma unroll
        for (int p = 0; p < 4; p++) {
            uint32_t bd = stg + boff + (uint32_t)(p * 16 * GKP) * 2;
            LDSM4(bF[0][2 * p][0], bF[0][2 * p][1],
                  bF[0][2 * p + 1][0], bF[0][2 * p + 1][1], bd);
        }

#pragma unroll
        for (int ks = 0; ks < 4; ks++) {
            const int cur = ks & 1, nxt = cur ^ 1;
            if (ks < 3) {
                // ---- prefetch fragments for ks+1 (overlaps MMAs below) ----
                const uint32_t kso = (uint32_t)((ks + 1) * 16) * 2;
#pragma unroll
                for (int mt = 0; mt < 2; mt++) {
                    uint32_t ad = stg + aoff + (uint32_t)(mt * 16 * GKP) * 2 + kso;
                    LDSM4(aF[nxt][mt][0], aF[nxt][mt][1],
                          aF[nxt][mt][2], aF[nxt][mt][3], ad);
                }
#pragma unroll
                for (int p = 0; p < 4; p++) {
                    uint32_t bd = stg + boff + (uint32_t)(p * 16 * GKP) * 2 + kso;
                    LDSM4(bF[nxt][2 * p][0], bF[nxt][2 * p][1],
                          bF[nxt][2 * p + 1][0], bF[nxt][2 * p + 1][1], bd);
                }
            }
            // ---- 16 MMAs on current buffer ----
#pragma unroll
            for (int mt = 0; mt < 2; mt++)
#pragma unroll
                for (int nt = 0; nt < 8; nt++)
                    MMAA(acc[mt][nt], aF[cur][mt], bF[cur][nt]);
        }
    }

#pragma unroll
    for (int mt = 0; mt < 2; mt++) {
        int row0 = brow + wm * 32 + mt * 16 + (lane >> 2);
#pragma unroll
        for (int nt = 0; nt < 8; nt++) {
            int col = bcol + wn * 64 + nt * 8 + ((lane & 3) << 1);
            float b0 = bias[col], b1 = bias[col + 1];
            float v00 = acc[mt][nt][0] + b0, v01 = acc[mt][nt][1] + b1;
            float v10 = acc[mt][nt][2] + b0, v11 = acc[mt][nt][3] + b1;
            if (FP16_OUT) {
                ((uint32_t*)Ch)[((size_t)row0 * N + col) >> 1] = pack_h2(v00, v01);
                ((uint32_t*)Ch)[((size_t)(row0 + 8) * N + col) >> 1] = pack_h2(v10, v11);
            } else {
                *(float2*)(C + (size_t)row0 * N + col) = make_float2(v00, v01);
                *(float2*)(C + (size_t)(row0 + 8) * N + col) = make_float2(v10, v11);
            }
        }
    }
}

// ---------------------------------------------------------------------------
// fp16 flash attention (round-11 version, unchanged).
// ---------------------------------------------------------------------------
#define TQ 128
#define TK 64
#define PR 72
#define QELE (TQ * PR)              /* 9216 */
#define STG_ELE (2 * TK * PR)       /* K + V: 9216 */
#define ANSTG 3
#define ASMEM ((QELE + ANSTG * STG_ELE) * 2)  /* 73728 B */

__global__ __launch_bounds__(256, 2) void attn_f16(
    const __half* __restrict__ qkv, __half* __restrict__ outf)
{
    extern __shared__ __half as[];
    const int tid = threadIdx.x;
    const int lane = tid & 31, warp = tid >> 5;
    const int qt = blockIdx.x, h = blockIdx.y, b = blockIdx.z;

    uint32_t sbase = (uint32_t)__cvta_generic_to_shared(as);

    const int a_r = lane & 15;
    const int a_k = (lane >> 4) << 3;
    const int bg = lane >> 3;
    const int b_r = ((bg & 2) << 2) + (lane & 7);
    const int b_k = (bg & 1) << 3;
    const int tb_k = ((bg & 1) << 3) + (lane & 7);
    const int tb_n = (bg & 2) << 2;

    const size_t qrow0 = ((size_t)b * SEQ + (size_t)qt * TQ);

    auto load_kv = [&](int st, int t) {
        size_t krow0 = (size_t)b * SEQ + (size_t)t * TK;
#pragma unroll
        for (int m = 0; m < 2; m++) {
            int gofs = (m == 0 ? INNER : 2 * INNER) + h * DHEAD;
#pragma unroll
            for (int i = 0; i < 2; i++) {
                int c = i * 256 + tid;
                int row = c >> 3, col8 = (c & 7) << 3;
                uint32_t dst = sbase +
                    (uint32_t)(QELE + st * STG_ELE + m * TK * PR + row * PR + col8) * 2;
                CPASYNC16(dst, qkv + (krow0 + row) * QKV_COLS + gofs + col8);
            }
        }
        asm volatile("cp.async.commit_group;");
    };

    {
#pragma unroll
        for (int i = 0; i < 4; i++) {
            int c = i * 256 + tid;
            int row = c >> 3, col8 = (c & 7) << 3;
            uint32_t dst = sbase + (uint32_t)(row * PR + col8) * 2;
            CPASYNC16(dst, qkv + (qrow0 + row) * QKV_COLS + h * DHEAD + col8);
        }
    }
    load_kv(0, 0);
    load_kv(1, 1);

    // ---- hoist Q fragments, pre-scaled by ATT_SCALE (exact in fp16) ----
    uint32_t aQ[4][4];
    asm volatile("cp.async.wait_group 1;");
    __syncthreads();
    {
        const __half2 s2 = __floats2half2_rn(ATT_SCALE, ATT_SCALE);
#pragma unroll
        for (int ks = 0; ks < 4; ks++) {
            uint32_t ad = sbase + (uint32_t)((warp * 16 + a_r) * PR + ks * 16 + a_k) * 2;
            LDSM4(aQ[ks][0], aQ[ks][1], aQ[ks][2], aQ[ks][3], ad);
#pragma unroll
            for (int j = 0; j < 4; j++) {
                __half2 q = *(__half2*)&aQ[ks][j];
                q = __hmul2(q, s2);
                aQ[ks][j] = *(uint32_t*)&q;
            }
        }
    }

    float acc_o[8][4] = {};
    float mrow[2] = {-1e30f, -1e30f};
    float lrow[2] = {0.f, 0.f};

    const int NT = SEQ / TK;
    for (int t = 0; t < NT; t++) {
        if (t + 1 < NT) {
            asm volatile("cp.async.wait_group 1;");
        } else {
            asm volatile("cp.async.wait_group 0;");
        }
        __syncthreads();

        if (t + 2 < NT)
            load_kv((t + 2) % ANSTG, t + 2);

        const int kb = QELE + (t % ANSTG) * STG_ELE;

        // ---- S = Q K^T (Q from registers, pre-scaled) ----
        float acc_s[8][4] = {};
#pragma unroll
        for (int ks = 0; ks < 4; ks++) {
            uint32_t bH[8][2];
#pragma unroll
            for (int p = 0; p < 4; p++) {
                uint32_t bd = sbase +
                    (uint32_t)(kb + (p * 16 + b_r) * PR + ks * 16 + b_k) * 2;
                LDSM4(bH[2 * p][0], bH[2 * p][1], bH[2 * p + 1][0], bH[2 * p + 1][1], bd);
            }
#pragma unroll
            for (int nt = 0; nt < 8; nt++)
                MMAA(acc_s[nt], aQ[ks], bH[nt]);
        }

        // ---- softmax critical part: max -> corr -> rescale O -> exps ----
        float corr[2];
#pragma unroll
        for (int r = 0; r < 2; r++) {
            float mx = -1e30f;
#pragma unroll
            for (int nt = 0; nt < 8; nt++)
                mx = fmaxf(mx, fmaxf(acc_s[nt][2 * r], acc_s[nt][2 * r + 1]));
            mx = fmaxf(mx, __shfl_xor_sync(0xffffffffu, mx, 1));
            mx = fmaxf(mx, __shfl_xor_sync(0xffffffffu, mx, 2));
            float mn = fmaxf(mrow[r], mx);
            corr[r] = __expf(mrow[r] - mn);
            mrow[r] = mn;
#pragma unroll
            for (int nt = 0; nt < 8; nt++) {
                acc_s[nt][2 * r] = __expf(acc_s[nt][2 * r] - mn);
                acc_s[nt][2 * r + 1] = __expf(acc_s[nt][2 * r + 1] - mn);
            }
#pragma unroll
            for (int nt = 0; nt < 8; nt++) {
                acc_o[nt][2 * r] *= corr[r];
                acc_o[nt][2 * r + 1] *= corr[r];
            }
        }

        // ---- O += P @ V ----
        const int vb = kb + TK * PR;
#pragma unroll
        for (int kc = 0; kc < 4; kc++) {
            uint32_t aP[4], vH[8][2];
#pragma unroll
            for (int j = 0; j < 4; j++) {
                int tile = 2 * kc + (j >> 1);
                int c0 = (j & 1) << 1;
                aP[j] = pack_h2(acc_s[tile][c0], acc_s[tile][c0 + 1]);
            }
#pragma unroll
            for (int p = 0; p < 4; p++) {
                uint32_t vd = sbase +
                    (uint32_t)(vb + (kc * 16 + tb_k) * PR + p * 16 + tb_n) * 2;
                LDSM4T(vH[2 * p][0], vH[2 * p][1], vH[2 * p + 1][0], vH[2 * p + 1][1], vd);
            }
#pragma unroll
            for (int nt = 0; nt < 8; nt++)
                MMAA(acc_o[nt], aP, vH[nt]);
        }

        // ---- deferred row-sum (off the critical chain) ----
#pragma unroll
        for (int r = 0; r < 2; r++) {
            float sum = 0.f;
#pragma unroll
            for (int nt = 0; nt < 8; nt++)
                sum += acc_s[nt][2 * r] + acc_s[nt][2 * r + 1];
            sum += __shfl_xor_sync(0xffffffffu, sum, 1);
            sum += __shfl_xor_sync(0xffffffffu, sum, 2);
            lrow[r] = lrow[r] * corr[r] + sum;
        }
    }

    // ---- epilogue: normalize, fp16 out [b n (h d)] ----
    float inv0 = 1.0f / lrow[0], inv1 = 1.0f / lrow[1];
    size_t row0 = qrow0 + warp * 16 + (lane >> 2);
#pragma unroll
    for (int nt = 0; nt < 8; nt++) {
        int col = h * DHEAD + nt * 8 + ((lane & 3) << 1);
        ((uint32_t*)outf)[(row0 * INNER + col) >> 1] =
            pack_h2(acc_o[nt][0] * inv0, acc_o[nt][1] * inv0);
        ((uint32_t*)outf)[((row0 + 8) * INNER + col) >> 1] =
            pack_h2(acc_o[nt][2] * inv1, acc_o[nt][3] * inv1);
    }
}

// ---------------------------------------------------------------------------
extern "C" void kernel_launch(void* const* d_in, const int* in_sizes, int n_in,
                              void* d_out, int out_size)
{
    const float* x     = (const float*)d_in[0];
    const float* w_qkv = (const float*)d_in[1];
    const float* b_qkv = (const float*)d_in[2];
    const float* w_out = (const float*)d_in[3];
    const float* b_out = (const float*)d_in[4];
    float* out = (float*)d_out;

    __half *xf, *qf, *of, *wqf, *wof;
    cudaGetSymbolAddress((void**)&xf, g_xf);
    cudaGetSymbolAddress((void**)&qf, g_qkvf);
    cudaGetSymbolAddress((void**)&of, g_of);
    cudaGetSymbolAddress((void**)&wqf, g_wqkvf);
    cudaGetSymbolAddress((void**)&wof, g_woutf);

    cudaFuncSetAttribute(gemm_f16<true>,
                         cudaFuncAttributeMaxDynamicSharedMemorySize, GSMEM);
    cudaFuncSetAttribute(gemm_f16<false>,
                         cudaFuncAttributeMaxDynamicSharedMemorySize, GSMEM);
    cudaFuncSetAttribute(attn_f16,
                         cudaFuncAttributeMaxDynamicSharedMemorySize, ASMEM);

    // 0) conversions
    cvt_f32_f16<<<(ROWS * DIM / 4 + 255) / 256, 256>>>(x, xf, ROWS * DIM / 4);
    transpose_cvt<<<dim3(QKV_COLS / 32, DIM / 32), dim3(32, 8)>>>(w_qkv, wqf, DIM, QKV_COLS);
    transpose_cvt<<<dim3(DIM / 32, INNER / 32), dim3(32, 8)>>>(w_out, wof, INNER, DIM);

    // 1) qkv = x @ w_qkv + b_qkv  (fp16 out)
    gemm_f16<true><<<dim3(QKV_COLS / GBN, ROWS / GBM), 256, GSMEM>>>(
        xf, wqf, b_qkv, nullptr, qf, ROWS, QKV_COLS, DIM);

    // 2) flash attention (fp16) -> fp16 [b n (h d)]
    attn_f16<<<dim3(SEQ / TQ, HEADS, BATCH), 256, ASMEM>>>(qf, of);

    // 3) out = attn @ w_out + b_out  (fp32 out)
    gemm_f16<false><<<dim3(DIM / GBN, ROWS / GBM), 256, GSMEM>>>(
        of, wof, b_out, out, nullptr, ROWS, DIM, INNER);
}

// round 13
// speedup vs baseline: 1.0204x; 1.0204x over previous
#include <cuda_runtime.h>
#include <cuda_fp16.h>
#include <cstdint>

#define BATCH 4
#define SEQ 2048
#define DIM 1024
#define HEADS 16
#define DHEAD 64
#define INNER 1024
#define ROWS (BATCH * SEQ)      /* 8192 */
#define QKV_COLS (3 * INNER)    /* 3072 */
#define ATT_SCALE 0.125f

// ---------------- scratch (device globals) ----------------------------------
__device__ __half g_xf[(size_t)ROWS * DIM];
__device__ __half g_qkvf[(size_t)ROWS * QKV_COLS];
__device__ __half g_of[(size_t)ROWS * INNER];
__device__ __half g_wqkvf[(size_t)QKV_COLS * DIM];  // [N][K]
__device__ __half g_woutf[(size_t)DIM * INNER];     // [N][K]

// ---------------------------------------------------------------------------
__device__ __forceinline__ uint32_t pack_h2(float a, float b) {
    __half2 h = __floats2half2_rn(a, b);
    return *(uint32_t*)&h;
}

// ---------------------------------------------------------------------------
// Fused conversion kernel: one launch does
//   [0, XB)            : x fp32 -> fp16 (8 elems/thread)
//   [XB, XB+QB)        : w_qkv [K][N] fp32 -> [N][K] fp16 (32x32 transpose)
//   [XB+QB, XB+QB+OB)  : w_out  [K][N] fp32 -> [N][K] fp16
// ---------------------------------------------------------------------------
#define XB (ROWS * DIM / 8 / 256)          /* 4096 blocks, 8 elems/thread */
#define QB ((QKV_COLS / 32) * (DIM / 32))  /* 3072 blocks */
#define OB ((DIM / 32) * (INNER / 32))     /* 1024 blocks */

__device__ __forceinline__ void transpose_tile(
    const float* __restrict__ W, __half* __restrict__ T,
    int K, int N, int tileN, int tileK, int tid)
{
    __shared__ float t[32][33];
    int n0 = tileN * 32, k0 = tileK * 32;
    int tx = tid & 31, ty = tid >> 5;    // 32 x 8
#pragma unroll
    for (int j = 0; j < 4; j++)
        t[ty + j * 8][tx] = W[(size_t)(k0 + ty + j * 8) * N + n0 + tx];
    __syncthreads();
#pragma unroll
    for (int j = 0; j < 4; j++) {
        float f = t[tx][ty + j * 8];
        T[(size_t)(n0 + ty + j * 8) * K + k0 + tx] = __float2half_rn(f);
    }
}

__global__ void fused_convert(const float* __restrict__ x,
                              const float* __restrict__ w_qkv,
                              const float* __restrict__ w_out,
                              __half* __restrict__ xf,
                              __half* __restrict__ wqf,
                              __half* __restrict__ wof)
{
    const int bid = blockIdx.x;
    const int tid = threadIdx.x;
    if (bid < XB) {
        // x conversion: 8 fp32 -> 8 fp16 per thread
        size_t i = ((size_t)bid * 256 + tid) * 2;   // float4 index, 2 per thread
        float4 v0 = ((const float4*)x)[i];
        float4 v1 = ((const float4*)x)[i + 1];
        uint4 o;
        o.x = pack_h2(v0.x, v0.y);
        o.y = pack_h2(v0.z, v0.w);
        o.z = pack_h2(v1.x, v1.y);
        o.w = pack_h2(v1.z, v1.w);
        ((uint4*)xf)[(size_t)bid * 256 + tid] = o;
    } else if (bid < XB + QB) {
        int t = bid - XB;
        transpose_tile(w_qkv, wqf, DIM, QKV_COLS, t % (QKV_COLS / 32),
                       t / (QKV_COLS / 32), tid);
    } else {
        int t = bid - XB - QB;
        transpose_tile(w_out, wof, INNER, DIM, t % (DIM / 32),
                       t / (DIM / 32), tid);
    }
}

// ---------------------------------------------------------------------------
#define LDSM4(r0, r1, r2, r3, addr)                                          \
    asm volatile("ldmatrix.sync.aligned.m8n8.x4.shared.b16 {%0,%1,%2,%3}, [%4];" \
                 : "=r"(r0), "=r"(r1), "=r"(r2), "=r"(r3) : "r"(addr))
#define LDSM4T(r0, r1, r2, r3, addr)                                         \
    asm volatile("ldmatrix.sync.aligned.m8n8.x4.trans.shared.b16 {%0,%1,%2,%3}, [%4];" \
                 : "=r"(r0), "=r"(r1), "=r"(r2), "=r"(r3) : "r"(addr))
#define MMAS(d, a0, a1, a2, a3, b0, b1)                                      \
    asm volatile("mma.sync.aligned.m16n8k16.row.col.f32.f16.f16.f32 "        \
                 "{%0,%1,%2,%3},{%4,%5,%6,%7},{%8,%9},{%0,%1,%2,%3};"        \
                 : "+f"(d[0]), "+f"(d[1]), "+f"(d[2]), "+f"(d[3])            \
                 : "r"(a0), "r"(a1), "r"(a2), "r"(a3), "r"(b0), "r"(b1))
#define MMAA(d, a, b)                                                        \
    MMAS(d, (a)[0], (a)[1], (a)[2], (a)[3], (b)[0], (b)[1])
#define CPASYNC16(dst, src)                                                  \
    asm volatile("cp.async.cg.shared.global [%0], [%1], 16;" :: "r"(dst), "l"(src))

// ---------------------------------------------------------------------------
// fp16 HMMA GEMM (round-8/10 config — at the HMMA ceiling; do not touch):
// BM=BN=128, BK=64, 8 warps (32x64 tile), 3-stage cp.async ring,
// one sync per chunk, 2 CTAs/SM (regs<=128).
// ---------------------------------------------------------------------------
#define GBM 128
#define GBN 128
#define GBK 64
#define GKP 72
#define GSTAGE (2 * GBM * GKP)
#define GNSTG 3
#define GSMEM (GNSTG * GSTAGE * 2)   /* 110592 bytes */

template <bool FP16_OUT>
__global__ __launch_bounds__(256, 2) void gemm_f16(
    const __half* __restrict__ A, const __half* __restrict__ B,
    const float* __restrict__ bias, float* __restrict__ C,
    __half* __restrict__ Ch, int M, int N, int K)
{
    extern __shared__ __half sm[];
    const int tid = threadIdx.x;
    const int lane = tid & 31, warp = tid >> 5;
    const int wm = warp >> 1, wn = warp & 1;
    const int brow = blockIdx.y * GBM, bcol = blockIdx.x * GBN;

    uint32_t sbase = (uint32_t)__cvta_generic_to_shared(sm);
    const int lrow = tid >> 3;
    const int lk = (tid & 7) << 3;

    float acc[2][8][4] = {};

    const int a_r = lane & 15;
    const int a_k = (lane >> 4) << 3;
    const int bg = lane >> 3;
    const int b_r = ((bg & 2) << 2) + (lane & 7);
    const int b_k = (bg & 1) << 3;
    const int NK = K / GBK;

    auto load_stage = [&](int st, int k0) {
        int base = st * GSTAGE;
#pragma unroll
        for (int i = 0; i < 4; i++) {
            int row = lrow + i * 32;
            uint32_t da = sbase + (uint32_t)(base + row * GKP + lk) * 2;
            CPASYNC16(da, A + (size_t)(brow + row) * K + k0 + lk);
            uint32_t db = sbase + (uint32_t)(base + GBM * GKP + row * GKP + lk) * 2;
            CPASYNC16(db, B + (size_t)(bcol + row) * K + k0 + lk);
        }
        asm volatile("cp.async.commit_group;");
    };

    load_stage(0, 0);
    load_stage(1, GBK);

    for (int kc = 0; kc < NK; kc++) {
        if (kc + 1 < NK) {
            asm volatile("cp.async.wait_group 1;");
        } else {
            asm volatile("cp.async.wait_group 0;");
        }
        __syncthreads();

        if (kc + 2 < NK)
            load_stage((kc + 2) % GNSTG, (kc + 2) * GBK);

        const int abase = (kc % GNSTG) * GSTAGE;
#pragma unroll
        for (int ks = 0; ks < 4; ks++) {
            uint32_t aH[2][4];
#pragma unroll
            for (int mt = 0; mt < 2; mt++) {
                uint32_t ad = sbase +
                    (uint32_t)(abase + (wm * 32 + mt * 16 + a_r) * GKP + ks * 16 + a_k) * 2;
                LDSM4(aH[mt][0], aH[mt][1], aH[mt][2], aH[mt][3], ad);
            }
#pragma unroll
            for (int half = 0; half < 2; half++) {
                uint32_t bH[4][2];
#pragma unroll
                for (int p = 0; p < 2; p++) {
                    uint32_t bd = sbase +
                        (uint32_t)(abase + GBM * GKP +
                                   (wn * 64 + half * 32 + p * 16 + b_r) * GKP +
                                   ks * 16 + b_k) * 2;
                    LDSM4(bH[2 * p][0], bH[2 * p][1], bH[2 * p + 1][0], bH[2 * p + 1][1], bd);
                }
#pragma unroll
                for (int mt = 0; mt < 2; mt++)
#pragma unroll
                    for (int j = 0; j < 4; j++)
                        MMAA(acc[mt][half * 4 + j], aH[mt], bH[j]);
            }
        }
    }

#pragma unroll
    for (int mt = 0; mt < 2; mt++) {
        int row0 = brow + wm * 32 + mt * 16 + (lane >> 2);
#pragma unroll
        for (int nt = 0; nt < 8; nt++) {
            int col = bcol + wn * 64 + nt * 8 + ((lane & 3) << 1);
            float b0 = bias[col], b1 = bias[col + 1];
            float v00 = acc[mt][nt][0] + b0, v01 = acc[mt][nt][1] + b1;
            float v10 = acc[mt][nt][2] + b0, v11 = acc[mt][nt][3] + b1;
            if (FP16_OUT) {
                ((uint32_t*)Ch)[((size_t)row0 * N + col) >> 1] = pack_h2(v00, v01);
                ((uint32_t*)Ch)[((size_t)(row0 + 8) * N + col) >> 1] = pack_h2(v10, v11);
            } else {
                *(float2*)(C + (size_t)row0 * N + col) = make_float2(v00, v01);
                *(float2*)(C + (size_t)(row0 + 8) * N + col) = make_float2(v10, v11);
            }
        }
    }
}

// ---------------------------------------------------------------------------
// fp16 flash attention (round-11 version — at the HMMA ceiling; unchanged).
// ---------------------------------------------------------------------------
#define TQ 128
#define TK 64
#define PR 72
#define QELE (TQ * PR)
#define STG_ELE (2 * TK * PR)
#define ANSTG 3
#define ASMEM ((QELE + ANSTG * STG_ELE) * 2)  /* 73728 B */

__global__ __launch_bounds__(256, 2) void attn_f16(
    const __half* __restrict__ qkv, __half* __restrict__ outf)
{
    extern __shared__ __half as[];
    const int tid = threadIdx.x;
    const int lane = tid & 31, warp = tid >> 5;
    const int qt = blockIdx.x, h = blockIdx.y, b = blockIdx.z;

    uint32_t sbase = (uint32_t)__cvta_generic_to_shared(as);

    const int a_r = lane & 15;
    const int a_k = (lane >> 4) << 3;
    const int bg = lane >> 3;
    const int b_r = ((bg & 2) << 2) + (lane & 7);
    const int b_k = (bg & 1) << 3;
    const int tb_k = ((bg & 1) << 3) + (lane & 7);
    const int tb_n = (bg & 2) << 2;

    const size_t qrow0 = ((size_t)b * SEQ + (size_t)qt * TQ);

    auto load_kv = [&](int st, int t) {
        size_t krow0 = (size_t)b * SEQ + (size_t)t * TK;
#pragma unroll
        for (int m = 0; m < 2; m++) {
            int gofs = (m == 0 ? INNER : 2 * INNER) + h * DHEAD;
#pragma unroll
            for (int i = 0; i < 2; i++) {
                int c = i * 256 + tid;
                int row = c >> 3, col8 = (c & 7) << 3;
                uint32_t dst = sbase +
                    (uint32_t)(QELE + st * STG_ELE + m * TK * PR + row * PR + col8) * 2;
                CPASYNC16(dst, qkv + (krow0 + row) * QKV_COLS + gofs + col8);
            }
        }
        asm volatile("cp.async.commit_group;");
    };

    {
#pragma unroll
        for (int i = 0; i < 4; i++) {
            int c = i * 256 + tid;
            int row = c >> 3, col8 = (c & 7) << 3;
            uint32_t dst = sbase + (uint32_t)(row * PR + col8) * 2;
            CPASYNC16(dst, qkv + (qrow0 + row) * QKV_COLS + h * DHEAD + col8);
        }
    }
    load_kv(0, 0);
    load_kv(1, 1);

    // ---- hoist Q fragments, pre-scaled by ATT_SCALE (exact in fp16) ----
    uint32_t aQ[4][4];
    asm volatile("cp.async.wait_group 1;");
    __syncthreads();
    {
        const __half2 s2 = __floats2half2_rn(ATT_SCALE, ATT_SCALE);
#pragma unroll
        for (int ks = 0; ks < 4; ks++) {
            uint32_t ad = sbase + (uint32_t)((warp * 16 + a_r) * PR + ks * 16 + a_k) * 2;
            LDSM4(aQ[ks][0], aQ[ks][1], aQ[ks][2], aQ[ks][3], ad);
#pragma unroll
            for (int j = 0; j < 4; j++) {
                __half2 q = *(__half2*)&aQ[ks][j];
                q = __hmul2(q, s2);
                aQ[ks][j] = *(uint32_t*)&q;
            }
        }
    }

    float acc_o[8][4] = {};
    float mrow[2] = {-1e30f, -1e30f};
    float lrow[2] = {0.f, 0.f};

    const int NT = SEQ / TK;
    for (int t = 0; t < NT; t++) {
        if (t + 1 < NT) {
            asm volatile("cp.async.wait_group 1;");
        } else {
            asm volatile("cp.async.wait_group 0;");
        }
        __syncthreads();

        if (t + 2 < NT)
            load_kv((t + 2) % ANSTG, t + 2);

        const int kb = QELE + (t % ANSTG) * STG_ELE;

        // ---- S = Q K^T (Q from registers, pre-scaled) ----
        float acc_s[8][4] = {};
#pragma unroll
        for (int ks = 0; ks < 4; ks++) {
            uint32_t bH[8][2];
#pragma unroll
            for (int p = 0; p < 4; p++) {
                uint32_t bd = sbase +
                    (uint32_t)(kb + (p * 16 + b_r) * PR + ks * 16 + b_k) * 2;
                LDSM4(bH[2 * p][0], bH[2 * p][1], bH[2 * p + 1][0], bH[2 * p + 1][1], bd);
            }
#pragma unroll
            for (int nt = 0; nt < 8; nt++)
                MMAA(acc_s[nt], aQ[ks], bH[nt]);
        }

        // ---- softmax critical part: max -> corr -> rescale O -> exps ----
        float corr[2];
#pragma unroll
        for (int r = 0; r < 2; r++) {
            float mx = -1e30f;
#pragma unroll
            for (int nt = 0; nt < 8; nt++)
                mx = fmaxf(mx, fmaxf(acc_s[nt][2 * r], acc_s[nt][2 * r + 1]));
            mx = fmaxf(mx, __shfl_xor_sync(0xffffffffu, mx, 1));
            mx = fmaxf(mx, __shfl_xor_sync(0xffffffffu, mx, 2));
            float mn = fmaxf(mrow[r], mx);
            corr[r] = __expf(mrow[r] - mn);
            mrow[r] = mn;
#pragma unroll
            for (int nt = 0; nt < 8; nt++) {
                acc_s[nt][2 * r] = __expf(acc_s[nt][2 * r] - mn);
                acc_s[nt][2 * r + 1] = __expf(acc_s[nt][2 * r + 1] - mn);
            }
#pragma unroll
            for (int nt = 0; nt < 8; nt++) {
                acc_o[nt][2 * r] *= corr[r];
                acc_o[nt][2 * r + 1] *= corr[r];
            }
        }

        // ---- O += P @ V ----
        const int vb = kb + TK * PR;
#pragma unroll
        for (int kc = 0; kc < 4; kc++) {
            uint32_t aP[4], vH[8][2];
#pragma unroll
            for (int j = 0; j < 4; j++) {
                int tile = 2 * kc + (j >> 1);
                int c0 = (j & 1) << 1;
                aP[j] = pack_h2(acc_s[tile][c0], acc_s[tile][c0 + 1]);
            }
#pragma unroll
            for (int p = 0; p < 4; p++) {
                uint32_t vd = sbase +
                    (uint32_t)(vb + (kc * 16 + tb_k) * PR + p * 16 + tb_n) * 2;
                LDSM4T(vH[2 * p][0], vH[2 * p][1], vH[2 * p + 1][0], vH[2 * p + 1][1], vd);
            }
#pragma unroll
            for (int nt = 0; nt < 8; nt++)
                MMAA(acc_o[nt], aP, vH[nt]);
        }

        // ---- deferred row-sum (off the critical chain) ----
#pragma unroll
        for (int r = 0; r < 2; r++) {
            float sum = 0.f;
#pragma unroll
            for (int nt = 0; nt < 8; nt++)
                sum += acc_s[nt][2 * r] + acc_s[nt][2 * r + 1];
            sum += __shfl_xor_sync(0xffffffffu, sum, 1);
            sum += __shfl_xor_sync(0xffffffffu, sum, 2);
            lrow[r] = lrow[r] * corr[r] + sum;
        }
    }

    // ---- epilogue: normalize, fp16 out [b n (h d)] ----
    float inv0 = 1.0f / lrow[0], inv1 = 1.0f / lrow[1];
    size_t row0 = qrow0 + warp * 16 + (lane >> 2);
#pragma unroll
    for (int nt = 0; nt < 8; nt++) {
        int col = h * DHEAD + nt * 8 + ((lane & 3) << 1);
        ((uint32_t*)outf)[(row0 * INNER + col) >> 1] =
            pack_h2(acc_o[nt][0] * inv0, acc_o[nt][1] * inv0);
        ((uint32_t*)outf)[((row0 + 8) * INNER + col) >> 1] =
            pack_h2(acc_o[nt][2] * inv1, acc_o[nt][3] * inv1);
    }
}

// ---------------------------------------------------------------------------
extern "C" void kernel_launch(void* const* d_in, const int* in_sizes, int n_in,
                              void* d_out, int out_size)
{
    const float* x     = (const float*)d_in[0];
    const float* w_qkv = (const float*)d_in[1];
    const float* b_qkv = (const float*)d_in[2];
    const float* w_out = (const float*)d_in[3];
    const float* b_out = (const float*)d_in[4];
    float* out = (float*)d_out;

    __half *xf, *qf, *of, *wqf, *wof;
    cudaGetSymbolAddress((void**)&xf, g_xf);
    cudaGetSymbolAddress((void**)&qf, g_qkvf);
    cudaGetSymbolAddress((void**)&of, g_of);
    cudaGetSymbolAddress((void**)&wqf, g_wqkvf);
    cudaGetSymbolAddress((void**)&wof, g_woutf);

    cudaFuncSetAttribute(gemm_f16<true>,
                         cudaFuncAttributeMaxDynamicSharedMemorySize, GSMEM);
    cudaFuncSetAttribute(gemm_f16<false>,
                         cudaFuncAttributeMaxDynamicSharedMemorySize, GSMEM);
    cudaFuncSetAttribute(attn_f16,
                         cudaFuncAttributeMaxDynamicSharedMemorySize, ASMEM);

    // 0) fused conversions: x cvt + both weight transposes in ONE launch
    fused_convert<<<XB + QB + OB, 256>>>(x, w_qkv, w_out, xf, wqf, wof);

    // 1) qkv = x @ w_qkv + b_qkv  (fp16 out)
    gemm_f16<true><<<dim3(QKV_COLS / GBN, ROWS / GBM), 256, GSMEM>>>(
        xf, wqf, b_qkv, nullptr, qf, ROWS, QKV_COLS, DIM);

    // 2) flash attention (fp16) -> fp16 [b n (h d)]
    attn_f16<<<dim3(SEQ / TQ, HEADS, BATCH), 256, ASMEM>>>(qf, of);

    // 3) out = attn @ w_out + b_out  (fp32 out)
    gemm_f16<false><<<dim3(DIM / GBN, ROWS / GBM), 256, GSMEM>>>(
        of, wof, b_out, out, nullptr, ROWS, DIM, INNER);
}

// round 14
// speedup vs baseline: 1.0233x; 1.0029x over previous
#include <cuda_runtime.h>
#include <cuda_fp16.h>
#include <cstdint>

#define BATCH 4
#define SEQ 2048
#define DIM 1024
#define HEADS 16
#define DHEAD 64
#define INNER 1024
#define ROWS (BATCH * SEQ)      /* 8192 */
#define QKV_COLS (3 * INNER)    /* 3072 */
#define ATT_SCALE 0.125f

// ---------------- scratch (device globals) ----------------------------------
__device__ __half g_xf[(size_t)ROWS * DIM];
__device__ __half g_qkvf[(size_t)ROWS * QKV_COLS];
__device__ __half g_of[(size_t)ROWS * INNER];
__device__ __half g_wqkvf[(size_t)QKV_COLS * DIM];  // [N][K]
__device__ __half g_woutf[(size_t)DIM * INNER];     // [N][K]

// ---------------- cross-phase sync state (zeroed in fused_convert) ----------
#define NQKV_TILES ((ROWS / 128) * (QKV_COLS / 128))   /* 1536 */
#define NATTN_TILES (16 * HEADS * BATCH)               /* 1024 */
#define NOUT_TILES ((ROWS / 128) * (DIM / 128))        /* 512  */
#define QKV_PER_BATCH ((ROWS / BATCH / 128) * (QKV_COLS / 128))  /* 384 */

__device__ int g_ctr[3];
__device__ int g_qkv_done[BATCH];
__device__ int g_attn_done[ROWS / 128];   /* 64 */

// ---------------------------------------------------------------------------
__device__ __forceinline__ uint32_t pack_h2(float a, float b) {
    __half2 h = __floats2half2_rn(a, b);
    return *(uint32_t*)&h;
}

// ---------------------------------------------------------------------------
// Fused conversion kernel + sync-state reset.
// ---------------------------------------------------------------------------
#define XB (ROWS * DIM / 8 / 256)          /* 4096 blocks */
#define QB ((QKV_COLS / 32) * (DIM / 32))  /* 3072 blocks */
#define OB ((DIM / 32) * (INNER / 32))     /* 1024 blocks */

__device__ __forceinline__ void transpose_tile(
    const float* __restrict__ W, __half* __restrict__ T,
    int K, int N, int tileN, int tileK, int tid)
{
    __shared__ float t[32][33];
    int n0 = tileN * 32, k0 = tileK * 32;
    int tx = tid & 31, ty = tid >> 5;
#pragma unroll
    for (int j = 0; j < 4; j++)
        t[ty + j * 8][tx] = W[(size_t)(k0 + ty + j * 8) * N + n0 + tx];
    __syncthreads();
#pragma unroll
    for (int j = 0; j < 4; j++) {
        float f = t[tx][ty + j * 8];
        T[(size_t)(n0 + ty + j * 8) * K + k0 + tx] = __float2half_rn(f);
    }
}

__global__ void fused_convert(const float* __restrict__ x,
                              const float* __restrict__ w_qkv,
                              const float* __restrict__ w_out,
                              __half* __restrict__ xf,
                              __half* __restrict__ wqf,
                              __half* __restrict__ wof)
{
    const int bid = blockIdx.x;
    const int tid = threadIdx.x;
    if (bid == 0) {
        // reset cross-phase sync state (stream-ordered before mega kernel)
        if (tid < 3) g_ctr[tid] = 0;
        if (tid >= 3 && tid < 3 + BATCH) g_qkv_done[tid - 3] = 0;
        if (tid >= 8 && tid < 8 + ROWS / 128) g_attn_done[tid - 8] = 0;
    }
    if (bid < XB) {
        size_t i = ((size_t)bid * 256 + tid) * 2;
        float4 v0 = ((const float4*)x)[i];
        float4 v1 = ((const float4*)x)[i + 1];
        uint4 o;
        o.x = pack_h2(v0.x, v0.y);
        o.y = pack_h2(v0.z, v0.w);
        o.z = pack_h2(v1.x, v1.y);
        o.w = pack_h2(v1.z, v1.w);
        ((uint4*)xf)[(size_t)bid * 256 + tid] = o;
    } else if (bid < XB + QB) {
        int t = bid - XB;
        transpose_tile(w_qkv, wqf, DIM, QKV_COLS, t % (QKV_COLS / 32),
                       t / (QKV_COLS / 32), tid);
    } else {
        int t = bid - XB - QB;
        transpose_tile(w_out, wof, INNER, DIM, t % (DIM / 32),
                       t / (DIM / 32), tid);
    }
}

// ---------------------------------------------------------------------------
#define LDSM4(r0, r1, r2, r3, addr)                                          \
    asm volatile("ldmatrix.sync.aligned.m8n8.x4.shared.b16 {%0,%1,%2,%3}, [%4];" \
                 : "=r"(r0), "=r"(r1), "=r"(r2), "=r"(r3) : "r"(addr))
#define LDSM4T(r0, r1, r2, r3, addr)                                         \
    asm volatile("ldmatrix.sync.aligned.m8n8.x4.trans.shared.b16 {%0,%1,%2,%3}, [%4];" \
                 : "=r"(r0), "=r"(r1), "=r"(r2), "=r"(r3) : "r"(addr))
#define MMAS(d, a0, a1, a2, a3, b0, b1)                                      \
    asm volatile("mma.sync.aligned.m16n8k16.row.col.f32.f16.f16.f32 "        \
                 "{%0,%1,%2,%3},{%4,%5,%6,%7},{%8,%9},{%0,%1,%2,%3};"        \
                 : "+f"(d[0]), "+f"(d[1]), "+f"(d[2]), "+f"(d[3])            \
                 : "r"(a0), "r"(a1), "r"(a2), "r"(a3), "r"(b0), "r"(b1))
#define MMAA(d, a, b)                                                        \
    MMAS(d, (a)[0], (a)[1], (a)[2], (a)[3], (b)[0], (b)[1])
#define CPASYNC16(dst, src)                                                  \
    asm volatile("cp.async.cg.shared.global [%0], [%1], 16;" :: "r"(dst), "l"(src))

// ---------------------------------------------------------------------------
// GEMM tile body (round-8 config, verbatim math): 128x128 tile, BK=64,
// 8 warps (32x64), 3-stage cp.async ring, one sync per chunk.
// ---------------------------------------------------------------------------
#define GBK 64
#define GKP 72
#define GSTAGE (2 * 128 * GKP)
#define GNSTG 3
#define GSMEM (GNSTG * GSTAGE * 2)   /* 110592 bytes */

template <bool FP16_OUT>
__device__ void gemm_tile(
    const __half* __restrict__ A, const __half* __restrict__ B,
    const float* __restrict__ bias, float* __restrict__ C,
    __half* __restrict__ Ch, int N, int K, int brow, int bcol,
    uint32_t sbase, int tid)
{
    const int lane = tid & 31, warp = tid >> 5;
    const int wm = warp >> 1, wn = warp & 1;
    const int lrow = tid >> 3;
    const int lk = (tid & 7) << 3;

    float acc[2][8][4] = {};

    const int a_r = lane & 15;
    const int a_k = (lane >> 4) << 3;
    const int bg = lane >> 3;
    const int b_r = ((bg & 2) << 2) + (lane & 7);
    const int b_k = (bg & 1) << 3;
    const int NK = K / GBK;

    auto load_stage = [&](int st, int k0) {
        int base = st * GSTAGE;
#pragma unroll
        for (int i = 0; i < 4; i++) {
            int row = lrow + i * 32;
            uint32_t da = sbase + (uint32_t)(base + row * GKP + lk) * 2;
            CPASYNC16(da, A + (size_t)(brow + row) * K + k0 + lk);
            uint32_t db = sbase + (uint32_t)(base + 128 * GKP + row * GKP + lk) * 2;
            CPASYNC16(db, B + (size_t)(bcol + row) * K + k0 + lk);
        }
        asm volatile("cp.async.commit_group;");
    };

    load_stage(0, 0);
    load_stage(1, GBK);

    for (int kc = 0; kc < NK; kc++) {
        if (kc + 1 < NK) {
            asm volatile("cp.async.wait_group 1;");
        } else {
            asm volatile("cp.async.wait_group 0;");
        }
        __syncthreads();

        if (kc + 2 < NK)
            load_stage((kc + 2) % GNSTG, (kc + 2) * GBK);

        const int abase = (kc % GNSTG) * GSTAGE;
#pragma unroll
        for (int ks = 0; ks < 4; ks++) {
            uint32_t aH[2][4];
#pragma unroll
            for (int mt = 0; mt < 2; mt++) {
                uint32_t ad = sbase +
                    (uint32_t)(abase + (wm * 32 + mt * 16 + a_r) * GKP + ks * 16 + a_k) * 2;
                LDSM4(aH[mt][0], aH[mt][1], aH[mt][2], aH[mt][3], ad);
            }
#pragma unroll
            for (int half = 0; half < 2; half++) {
                uint32_t bH[4][2];
#pragma unroll
                for (int p = 0; p < 2; p++) {
                    uint32_t bd = sbase +
                        (uint32_t)(abase + 128 * GKP +
                                   (wn * 64 + half * 32 + p * 16 + b_r) * GKP +
                                   ks * 16 + b_k) * 2;
                    LDSM4(bH[2 * p][0], bH[2 * p][1], bH[2 * p + 1][0], bH[2 * p + 1][1], bd);
                }
#pragma unroll
                for (int mt = 0; mt < 2; mt++)
#pragma unroll
                    for (int j = 0; j < 4; j++)
                        MMAA(acc[mt][half * 4 + j], aH[mt], bH[j]);
            }
        }
    }
    __syncthreads();   // smem idle before next tile reuses it

#pragma unroll
    for (int mt = 0; mt < 2; mt++) {
        int row0 = brow + wm * 32 + mt * 16 + (lane >> 2);
#pragma unroll
        for (int nt = 0; nt < 8; nt++) {
            int col = bcol + wn * 64 + nt * 8 + ((lane & 3) << 1);
            float b0 = bias[col], b1 = bias[col + 1];
            float v00 = acc[mt][nt][0] + b0, v01 = acc[mt][nt][1] + b1;
            float v10 = acc[mt][nt][2] + b0, v11 = acc[mt][nt][3] + b1;
            if (FP16_OUT) {
                ((uint32_t*)Ch)[((size_t)row0 * N + col) >> 1] = pack_h2(v00, v01);
                ((uint32_t*)Ch)[((size_t)(row0 + 8) * N + col) >> 1] = pack_h2(v10, v11);
            } else {
                *(float2*)(C + (size_t)row0 * N + col) = make_float2(v00, v01);
                *(float2*)(C + (size_t)(row0 + 8) * N + col) = make_float2(v10, v11);
            }
        }
    }
}

// ---------------------------------------------------------------------------
// Attention tile body (round-11/13, verbatim math).
// ---------------------------------------------------------------------------
#define TQ 128
#define TK 64
#define PR 72
#define QELE (TQ * PR)
#define STG_ELE (2 * TK * PR)
#define ANSTG 3

__device__ void attn_tile(const __half* __restrict__ qkv,
                          __half* __restrict__ outf,
                          int qt, int h, int b, uint32_t sbase, int tid)
{
    const int lane = tid & 31, warp = tid >> 5;

    const int a_r = lane & 15;
    const int a_k = (lane >> 4) << 3;
    const int bg = lane >> 3;
    const int b_r = ((bg & 2) << 2) + (lane & 7);
    const int b_k = (bg & 1) << 3;
    const int tb_k = ((bg & 1) << 3) + (lane & 7);
    const int tb_n = (bg & 2) << 2;

    const size_t qrow0 = ((size_t)b * SEQ + (size_t)qt * TQ);

    auto load_kv = [&](int st, int t) {
        size_t krow0 = (size_t)b * SEQ + (size_t)t * TK;
#pragma unroll
        for (int m = 0; m < 2; m++) {
            int gofs = (m == 0 ? INNER : 2 * INNER) + h * DHEAD;
#pragma unroll
            for (int i = 0; i < 2; i++) {
                int c = i * 256 + tid;
                int row = c >> 3, col8 = (c & 7) << 3;
                uint32_t dst = sbase +
                    (uint32_t)(QELE + st * STG_ELE + m * TK * PR + row * PR + col8) * 2;
                CPASYNC16(dst, qkv + (krow0 + row) * QKV_COLS + gofs + col8);
            }
        }
        asm volatile("cp.async.commit_group;");
    };

    {
#pragma unroll
        for (int i = 0; i < 4; i++) {
            int c = i * 256 + tid;
            int row = c >> 3, col8 = (c & 7) << 3;
            uint32_t dst = sbase + (uint32_t)(row * PR + col8) * 2;
            CPASYNC16(dst, qkv + (qrow0 + row) * QKV_COLS + h * DHEAD + col8);
        }
    }
    load_kv(0, 0);
    load_kv(1, 1);

    uint32_t aQ[4][4];
    asm volatile("cp.async.wait_group 1;");
    __syncthreads();
    {
        const __half2 s2 = __floats2half2_rn(ATT_SCALE, ATT_SCALE);
#pragma unroll
        for (int ks = 0; ks < 4; ks++) {
            uint32_t ad = sbase + (uint32_t)((warp * 16 + a_r) * PR + ks * 16 + a_k) * 2;
            LDSM4(aQ[ks][0], aQ[ks][1], aQ[ks][2], aQ[ks][3], ad);
#pragma unroll
            for (int j = 0; j < 4; j++) {
                __half2 q = *(__half2*)&aQ[ks][j];
                q = __hmul2(q, s2);
                aQ[ks][j] = *(uint32_t*)&q;
            }
        }
    }

    float acc_o[8][4] = {};
    float mrow[2] = {-1e30f, -1e30f};
    float lrow[2] = {0.f, 0.f};

    const int NT = SEQ / TK;
    for (int t = 0; t < NT; t++) {
        if (t + 1 < NT) {
            asm volatile("cp.async.wait_group 1;");
        } else {
            asm volatile("cp.async.wait_group 0;");
        }
        __syncthreads();

        if (t + 2 < NT)
            load_kv((t + 2) % ANSTG, t + 2);

        const int kb = QELE + (t % ANSTG) * STG_ELE;

        float acc_s[8][4] = {};
#pragma unroll
        for (int ks = 0; ks < 4; ks++) {
            uint32_t bH[8][2];
#pragma unroll
            for (int p = 0; p < 4; p++) {
                uint32_t bd = sbase +
                    (uint32_t)(kb + (p * 16 + b_r) * PR + ks * 16 + b_k) * 2;
                LDSM4(bH[2 * p][0], bH[2 * p][1], bH[2 * p + 1][0], bH[2 * p + 1][1], bd);
            }
#pragma unroll
            for (int nt = 0; nt < 8; nt++)
                MMAA(acc_s[nt], aQ[ks], bH[nt]);
        }

        float corr[2];
#pragma unroll
        for (int r = 0; r < 2; r++) {
            float mx = -1e30f;
#pragma unroll
            for (int nt = 0; nt < 8; nt++)
                mx = fmaxf(mx, fmaxf(acc_s[nt][2 * r], acc_s[nt][2 * r + 1]));
            mx = fmaxf(mx, __shfl_xor_sync(0xffffffffu, mx, 1));
            mx = fmaxf(mx, __shfl_xor_sync(0xffffffffu, mx, 2));
            float mn = fmaxf(mrow[r], mx);
            corr[r] = __expf(mrow[r] - mn);
            mrow[r] = mn;
#pragma unroll
            for (int nt = 0; nt < 8; nt++) {
                acc_s[nt][2 * r] = __expf(acc_s[nt][2 * r] - mn);
                acc_s[nt][2 * r + 1] = __expf(acc_s[nt][2 * r + 1] - mn);
            }
#pragma unroll
            for (int nt = 0; nt < 8; nt++) {
                acc_o[nt][2 * r] *= corr[r];
                acc_o[nt][2 * r + 1] *= corr[r];
            }
        }

        const int vb = kb + TK * PR;
#pragma unroll
        for (int kc = 0; kc < 4; kc++) {
            uint32_t aP[4], vH[8][2];
#pragma unroll
            for (int j = 0; j < 4; j++) {
                int tile = 2 * kc + (j >> 1);
                int c0 = (j & 1) << 1;
                aP[j] = pack_h2(acc_s[tile][c0], acc_s[tile][c0 + 1]);
            }
#pragma unroll
            for (int p = 0; p < 4; p++) {
                uint32_t vd = sbase +
                    (uint32_t)(vb + (kc * 16 + tb_k) * PR + p * 16 + tb_n) * 2;
                LDSM4T(vH[2 * p][0], vH[2 * p][1], vH[2 * p + 1][0], vH[2 * p + 1][1], vd);
            }
#pragma unroll
            for (int nt = 0; nt < 8; nt++)
                MMAA(acc_o[nt], aP, vH[nt]);
        }

#pragma unroll
        for (int r = 0; r < 2; r++) {
            float sum = 0.f;
#pragma unroll
            for (int nt = 0; nt < 8; nt++)
                sum += acc_s[nt][2 * r] + acc_s[nt][2 * r + 1];
            sum += __shfl_xor_sync(0xffffffffu, sum, 1);
            sum += __shfl_xor_sync(0xffffffffu, sum, 2);
            lrow[r] = lrow[r] * corr[r] + sum;
        }
    }
    __syncthreads();   // smem idle before next tile reuses it

    float inv0 = 1.0f / lrow[0], inv1 = 1.0f / lrow[1];
    size_t row0 = qrow0 + warp * 16 + (lane >> 2);
#pragma unroll
    for (int nt = 0; nt < 8; nt++) {
        int col = h * DHEAD + nt * 8 + ((lane & 3) << 1);
        ((uint32_t*)outf)[(row0 * INNER + col) >> 1] =
            pack_h2(acc_o[nt][0] * inv0, acc_o[nt][1] * inv0);
        ((uint32_t*)outf)[((row0 + 8) * INNER + col) >> 1] =
            pack_h2(acc_o[nt][2] * inv1, acc_o[nt][3] * inv1);
    }
}

// ---------------------------------------------------------------------------
// Persistent fused kernel: phase 1 QKV GEMM -> phase 2 attention -> phase 3
// out-proj, with atomic claims + release/acquire flags. Deadlock-free: a CTA
// enters a waiting phase only after ALL prior-phase tiles are claimed, and
// phase-1 claimants never wait.
// ---------------------------------------------------------------------------
__global__ __launch_bounds__(256, 2) void mega(
    const float* __restrict__ b_qkv, const float* __restrict__ b_out,
    float* __restrict__ out)
{
    extern __shared__ __half sm[];
    uint32_t sbase = (uint32_t)__cvta_generic_to_shared(sm);
    const int tid = threadIdx.x;
    __shared__ int s_slot;

    __half* xf = g_xf;
    __half* qf = g_qkvf;
    __half* of = g_of;
    __half* wqf = g_wqkvf;
    __half* wof = g_woutf;

    // ---- phase 1: QKV GEMM (batch-ascending claim order) ----
    for (;;) {
        if (tid == 0) s_slot = atomicAdd(&g_ctr[0], 1);
        __syncthreads();
        int t = s_slot;
        __syncthreads();
        if (t >= NQKV_TILES) break;
        int rowblk = t / (QKV_COLS / 128);
        int colblk = t % (QKV_COLS / 128);
        gemm_tile<true>(xf, wqf, b_qkv, nullptr, qf,
                        QKV_COLS, DIM, rowblk * 128, colblk * 128, sbase, tid);
        __syncthreads();
        if (tid == 0) {
            __threadfence();
            atomicAdd(&g_qkv_done[rowblk / (ROWS / BATCH / 128)], 1);
        }
    }

    // ---- phase 2: attention (waits on per-batch qkv completion) ----
    for (;;) {
        if (tid == 0) s_slot = atomicAdd(&g_ctr[1], 1);
        __syncthreads();
        int t = s_slot;
        __syncthreads();
        if (t >= NATTN_TILES) break;
        int b = t / (16 * HEADS);
        int r = t % (16 * HEADS);
        int qt = r / HEADS, h = r % HEADS;
        if (tid == 0) {
            while (atomicAdd(&g_qkv_done[b], 0) < QKV_PER_BATCH) __nanosleep(200);
        }
        __syncthreads();
        __threadfence();   // acquire
        attn_tile(qf, of, qt, h, b, sbase, tid);
        __syncthreads();
        if (tid == 0) {
            __threadfence();
            atomicAdd(&g_attn_done[b * 16 + qt], 1);
        }
    }

    // ---- phase 3: out-proj GEMM (waits on per-rowblock attention) ----
    for (;;) {
        if (tid == 0) s_slot = atomicAdd(&g_ctr[2], 1);
        __syncthreads();
        int t = s_slot;
        __syncthreads();
        if (t >= NOUT_TILES) break;
        int rowblk = t / (DIM / 128);
        int colblk = t % (DIM / 128);
        if (tid == 0) {
            while (atomicAdd(&g_attn_done[rowblk], 0) < HEADS) __nanosleep(200);
        }
        __syncthreads();
        __threadfence();   // acquire
        gemm_tile<false>(of, wof, b_out, out, nullptr,
                         DIM, INNER, rowblk * 128, colblk * 128, sbase, tid);
        __syncthreads();
    }
}

// ---------------------------------------------------------------------------
extern "C" void kernel_launch(void* const* d_in, const int* in_sizes, int n_in,
                              void* d_out, int out_size)
{
    const float* x     = (const float*)d_in[0];
    const float* w_qkv = (const float*)d_in[1];
    const float* b_qkv = (const float*)d_in[2];
    const float* w_out = (const float*)d_in[3];
    const float* b_out = (const float*)d_in[4];
    float* out = (float*)d_out;

    __half *xf, *wqf, *wof;
    cudaGetSymbolAddress((void**)&xf, g_xf);
    cudaGetSymbolAddress((void**)&wqf, g_wqkvf);
    cudaGetSymbolAddress((void**)&wof, g_woutf);

    int nsm = 148;
    cudaDeviceGetAttribute(&nsm, cudaDevAttrMultiProcessorCount, 0);

    cudaFuncSetAttribute(mega, cudaFuncAttributeMaxDynamicSharedMemorySize, GSMEM);

    // 0) fused conversions + sync-state reset (one launch)
    fused_convert<<<XB + QB + OB, 256>>>(x, w_qkv, w_out, xf, wqf, wof);

    // 1) persistent fused QKV -> attention -> out-proj
    mega<<<nsm * 2, 256, GSMEM>>>(b_qkv, b_out, out);
}